// round 11
// baseline (speedup 1.0000x reference)
#include <cuda_runtime.h>
#include <cuda_bf16.h>
#include <cstdint>

#define B_  16
#define C_  512
#define HW  1024
// 512^-0.5 * log2(e): scores land in log2 domain -> softmax uses raw ex2
#define QSCALE_F 0.06376237874911709f

// ---------------- scratch (device globals) ----------------
__device__ __nv_bfloat16 g_hT  [(size_t)B_ * HW * C_];      // [b][pos][ch]
__device__ __nv_bfloat16 g_qkvT[(size_t)B_ * HW * 3 * C_];  // [b][pos][och], q pre-scaled by QSCALE
__device__ __nv_bfloat16 g_attnT[(size_t)B_ * HW * C_];     // [b][pos][ch] (head-major permuted)
__device__ __nv_bfloat16 g_wqkv[(size_t)3 * C_ * C_];       // [och][ch]
__device__ __nv_bfloat16 g_wproj[(size_t)C_ * C_];          // [och][ch]

// ---------------- helpers ----------------
__device__ __forceinline__ uint32_t smem_u32(const void* p) {
    uint32_t a;
    asm("{ .reg .u64 t; cvta.to.shared.u64 t, %1; cvt.u32.u64 %0, t; }" : "=r"(a) : "l"(p));
    return a;
}
#define CP16(dst, src) asm volatile("cp.async.cg.shared.global [%0], [%1], 16;" :: "r"(dst), "l"(src))
#define CP_COMMIT()    asm volatile("cp.async.commit_group;" ::: "memory")
#define CP_WAIT(n)     asm volatile("cp.async.wait_group %0;" :: "n"(n) : "memory")

__device__ __forceinline__ void ldm_x4(uint32_t* r, uint32_t a) {
    asm volatile("ldmatrix.sync.aligned.m8n8.x4.shared.b16 {%0,%1,%2,%3}, [%4];"
        : "=r"(r[0]), "=r"(r[1]), "=r"(r[2]), "=r"(r[3]) : "r"(a));
}
__device__ __forceinline__ void ldm_x4t(uint32_t* r, uint32_t a) {
    asm volatile("ldmatrix.sync.aligned.m8n8.x4.trans.shared.b16 {%0,%1,%2,%3}, [%4];"
        : "=r"(r[0]), "=r"(r[1]), "=r"(r[2]), "=r"(r[3]) : "r"(a));
}
__device__ __forceinline__ void mma_bf16(float* d, const uint32_t* a, uint32_t b0, uint32_t b1) {
    asm volatile("mma.sync.aligned.m16n8k16.row.col.f32.bf16.bf16.f32 "
        "{%0,%1,%2,%3}, {%4,%5,%6,%7}, {%8,%9}, {%0,%1,%2,%3};"
        : "+f"(d[0]), "+f"(d[1]), "+f"(d[2]), "+f"(d[3])
        : "r"(a[0]), "r"(a[1]), "r"(a[2]), "r"(a[3]), "r"(b0), "r"(b1));
}
__device__ __forceinline__ uint32_t pack_bf2(float lo, float hi) {
    __nv_bfloat162 t = __floats2bfloat162_rn(lo, hi);
    return *(uint32_t*)&t;
}
__device__ __forceinline__ float ex2f(float x) {
    float r;
    asm("ex2.approx.ftz.f32 %0, %1;" : "=f"(r) : "f"(x));
    return r;
}

// ---------------- GroupNorm -> transposed bf16 (+ fused weight convert) ----------------
__global__ __launch_bounds__(256) void gn_kernel(const float* __restrict__ x,
                                                 const float* __restrict__ gamma,
                                                 const float* __restrict__ beta,
                                                 const float* __restrict__ wq,
                                                 const float* __restrict__ wp) {
    int bg = blockIdx.x;
    int b = bg >> 5, g = bg & 31;

    // fused weight conversion: 2048 elements per block (1,048,576 total / 512 blocks)
    {
        int base = bg * 2048 + threadIdx.x;
        #pragma unroll
        for (int i = 0; i < 8; i++) {
            int idx = base + i * 256;
            if (idx < 3 * C_ * C_) g_wqkv[idx] = __float2bfloat16_rn(wq[idx]);
            else                   g_wproj[idx - 3 * C_ * C_] = __float2bfloat16_rn(wp[idx - 3 * C_ * C_]);
        }
    }

    const float* xp = x + ((size_t)b * C_ + g * 16) * HW;
    float s = 0.f, s2 = 0.f;
    for (int i = threadIdx.x; i < 16 * HW; i += 256) { float v = xp[i]; s += v; s2 += v * v; }
    __shared__ float rs[256], rs2[256];
    __shared__ float sgam[16], sbet[16];
    rs[threadIdx.x] = s; rs2[threadIdx.x] = s2;
    if (threadIdx.x < 16) { sgam[threadIdx.x] = gamma[g * 16 + threadIdx.x];
                            sbet[threadIdx.x] = beta [g * 16 + threadIdx.x]; }
    __syncthreads();
    for (int o = 128; o > 0; o >>= 1) {
        if (threadIdx.x < o) { rs[threadIdx.x] += rs[threadIdx.x + o]; rs2[threadIdx.x] += rs2[threadIdx.x + o]; }
        __syncthreads();
    }
    float mean = rs[0] * (1.f / 16384.f);
    float var  = rs2[0] * (1.f / 16384.f) - mean * mean;
    float inv  = rsqrtf(var + 1e-5f);
    for (int pp = 0; pp < 4; pp++) {
        int pos = pp * 256 + threadIdx.x;
        __nv_bfloat16 o16[16];
        #pragma unroll
        for (int c = 0; c < 16; c++)
            o16[c] = __float2bfloat16_rn((xp[c * HW + pos] - mean) * inv * sgam[c] + sbet[c]);
        __nv_bfloat16* dst = g_hT + ((size_t)b * HW + pos) * C_ + g * 16;
        *(uint4*)dst       = *(uint4*)&o16[0];
        *(uint4*)(dst + 8) = *(uint4*)&o16[8];
    }
}

// ---------------- GEMM via mma.sync: tile 128x128, k-chunk 32, DB, 1 sync/iter ---------------
// __launch_bounds__(256,3): cap regs at 85 -> 3 CTAs/SM (vs 2 at 104 regs).
// pitch 80B; A stages @0/@10240, B stages @20480/@30720; total 40960 (x3 = 120KB/SM OK)
#define GEMM_SMEM 40960

__global__ __launch_bounds__(256, 3) void gemm_kernel(int mode, const float* __restrict__ bias,
                                                      const float* __restrict__ xres,
                                                      float* __restrict__ out) {
    extern __shared__ char smraw[];
    uint32_t sbase = smem_u32(smraw);
    int b = blockIdx.z;
    int n0 = blockIdx.x * 128, m0 = blockIdx.y * 128;
    const __nv_bfloat16 *gA, *gB;
    if (mode == 0) { gA = g_hT + ((size_t)b * HW + m0) * C_;  gB = g_wqkv + (size_t)n0 * C_; }
    else           { gA = g_wproj + (size_t)m0 * C_;          gB = g_attnT + ((size_t)b * HW + n0) * C_; }

    int tid = threadIdx.x, w = tid >> 5, lane = tid & 31;
    int wm = w >> 1, wn = w & 1;

    float acc[2][8][4];
    #pragma unroll
    for (int mt = 0; mt < 2; mt++)
        #pragma unroll
        for (int nt = 0; nt < 8; nt++)
            #pragma unroll
            for (int q = 0; q < 4; q++) acc[mt][nt][q] = 0.f;

    int lrow = tid >> 1, lcc = (tid & 1) * 2;
    const __nv_bfloat16* gArow = gA + (size_t)lrow * C_ + lcc * 8;
    const __nv_bfloat16* gBrow = gB + (size_t)lrow * C_ + lcc * 8;
    uint32_t sA = sbase + lrow * 80 + lcc * 16;
    uint32_t sB = sbase + 20480 + lrow * 80 + lcc * 16;

    CP16(sA, gArow); CP16(sA + 16, gArow + 8);
    CP16(sB, gBrow); CP16(sB + 16, gBrow + 8);
    CP_COMMIT();

    int arow = lane & 15, asel = lane >> 4;
    int bnrow = (lane & 7) + ((lane >> 4) << 3), bcsel = (lane >> 3) & 1;

    for (int kc = 0; kc < 16; kc++) {
        int st = kc & 1;
        CP_WAIT(0);
        __syncthreads();
        if (kc < 15) {
            int nst = st ^ 1;
            const __nv_bfloat16* a2 = gArow + (kc + 1) * 32;
            const __nv_bfloat16* b2 = gBrow + (kc + 1) * 32;
            uint32_t dA = sA + nst * 10240, dB = sB + nst * 10240;
            CP16(dA, a2); CP16(dA + 16, a2 + 8);
            CP16(dB, b2); CP16(dB + 16, b2 + 8);
            CP_COMMIT();
        }
        uint32_t Ab = sbase + st * 10240;
        uint32_t Bb = sbase + 20480 + st * 10240;
        #pragma unroll
        for (int j = 0; j < 2; j++) {
            uint32_t af[2][4];
            #pragma unroll
            for (int mt = 0; mt < 2; mt++)
                ldm_x4(af[mt], Ab + (wm * 32 + mt * 16 + arow) * 80 + (j * 2 + asel) * 16);
            #pragma unroll
            for (int p = 0; p < 4; p++) {
                uint32_t bf[4];
                ldm_x4(bf, Bb + (wn * 64 + p * 16 + bnrow) * 80 + (j * 2 + bcsel) * 16);
                #pragma unroll
                for (int mt = 0; mt < 2; mt++) {
                    mma_bf16(acc[mt][2 * p],     af[mt], bf[0], bf[1]);
                    mma_bf16(acc[mt][2 * p + 1], af[mt], bf[2], bf[3]);
                }
            }
        }
    }

    int r0 = m0 + wm * 32 + (lane >> 2);
    if (mode == 0) {
        #pragma unroll
        for (int mt = 0; mt < 2; mt++) {
            int r = r0 + mt * 16;
            #pragma unroll
            for (int nt = 0; nt < 8; nt++) {
                int col = n0 + wn * 64 + nt * 8 + (lane & 3) * 2;
                float b0v = bias[col], b1v = bias[col + 1];
                float sc = ((col % 192) < 64) ? QSCALE_F : 1.f;
                *(__nv_bfloat162*)&g_qkvT[((size_t)b * HW + r) * 1536 + col] =
                    __floats2bfloat162_rn((acc[mt][nt][0] + b0v) * sc, (acc[mt][nt][1] + b1v) * sc);
                *(__nv_bfloat162*)&g_qkvT[((size_t)b * HW + r + 8) * 1536 + col] =
                    __floats2bfloat162_rn((acc[mt][nt][2] + b0v) * sc, (acc[mt][nt][3] + b1v) * sc);
            }
        }
    } else {
        #pragma unroll
        for (int mt = 0; mt < 2; mt++) {
            int r = r0 + mt * 16;
            float bi0 = bias[r], bi1 = bias[r + 8];
            #pragma unroll
            for (int nt = 0; nt < 8; nt++) {
                int col = n0 + wn * 64 + nt * 8 + (lane & 3) * 2;
                float2 xa = *(const float2*)(xres + ((size_t)b * C_ + r) * HW + col);
                float2 xb = *(const float2*)(xres + ((size_t)b * C_ + r + 8) * HW + col);
                float2 o0 = { acc[mt][nt][0] + bi0 + xa.x, acc[mt][nt][1] + bi0 + xa.y };
                float2 o1 = { acc[mt][nt][2] + bi1 + xb.x, acc[mt][nt][3] + bi1 + xb.y };
                *(float2*)(out + ((size_t)b * C_ + r) * HW + col)     = o0;
                *(float2*)(out + ((size_t)b * C_ + r + 8) * HW + col) = o1;
            }
        }
    }
}

// ---------------- fused attention (R7: flash-style, log2 softmax, exp/mma overlap, DB) --------
// smem: Q[128][144B]@0 (18432), K stages @18432+st*9216, V stages @36864+st*9216; total 55296
#define QPITCH 144
#define ATTN_SMEM 55296

__global__ __launch_bounds__(256) void attn_kernel() {
    extern __shared__ char smraw[];
    uint32_t sbase = smem_u32(smraw);
    int bh = blockIdx.y, bb = bh >> 3, head = bh & 7;
    int q0 = blockIdx.x * 128;
    int tid = threadIdx.x, w = tid >> 5, lane = tid & 31;
    const __nv_bfloat16* qkvb = g_qkvT + (size_t)bb * HW * 1536;
    int hb = head * 192;

    // Q tile (q pre-scaled by 512^-0.5 * log2e in qkv epilogue)
    {
        int row = tid >> 1, c0 = (tid & 1) * 4;
        const __nv_bfloat16* src = qkvb + (size_t)(q0 + row) * 1536 + hb + c0 * 8;
        uint32_t dst = sbase + row * QPITCH + c0 * 16;
        CP16(dst, src); CP16(dst + 16, src + 8); CP16(dst + 32, src + 16); CP16(dst + 48, src + 24);
    }
    int kvrow = tid >> 2, kvc = (tid & 3) * 2;
    const __nv_bfloat16* gK = qkvb + hb + 64;
    const __nv_bfloat16* gV = qkvb + hb + 128;
    {
        const __nv_bfloat16* ks = gK + (size_t)kvrow * 1536 + kvc * 8;
        const __nv_bfloat16* vs = gV + (size_t)kvrow * 1536 + kvc * 8;
        uint32_t kd = sbase + 18432 + kvrow * QPITCH + kvc * 16;
        uint32_t vd = sbase + 36864 + kvrow * QPITCH + kvc * 16;
        CP16(kd, ks); CP16(kd + 16, ks + 8);
        CP16(vd, vs); CP16(vd + 16, vs + 8);
    }
    CP_COMMIT();

    uint32_t qf[4][4];
    float oacc[8][4];
    #pragma unroll
    for (int nt = 0; nt < 8; nt++)
        #pragma unroll
        for (int q = 0; q < 4; q++) oacc[nt][q] = 0.f;
    float l0 = 0.f, l1 = 0.f;

    int arow = lane & 15, asel = lane >> 4;
    int bnrow = (lane & 7) + ((lane >> 4) << 3), bcsel = (lane >> 3) & 1; // K non-trans
    int vkey  = (lane & 7) + (((lane >> 3) & 1) << 3), vcsel = lane >> 4; // V trans

    for (int kc = 0; kc < 16; kc++) {
        int st = kc & 1;
        CP_WAIT(0);
        __syncthreads();
        if (kc == 0) {   // Q resident: load register fragments once
            #pragma unroll
            for (int j = 0; j < 4; j++)
                ldm_x4(qf[j], sbase + (w * 16 + arow) * QPITCH + (j * 2 + asel) * 16);
        }
        if (kc < 15) {
            int nst = st ^ 1;
            const __nv_bfloat16* ks = gK + (size_t)((kc + 1) * 64 + kvrow) * 1536 + kvc * 8;
            const __nv_bfloat16* vs = gV + (size_t)((kc + 1) * 64 + kvrow) * 1536 + kvc * 8;
            uint32_t kd = sbase + 18432 + nst * 9216 + kvrow * QPITCH + kvc * 16;
            uint32_t vd = sbase + 36864 + nst * 9216 + kvrow * QPITCH + kvc * 16;
            CP16(kd, ks); CP16(kd + 16, ks + 8);
            CP16(vd, vs); CP16(vd + 16, vs + 8);
            CP_COMMIT();
        }

        uint32_t Kb = sbase + 18432 + st * 9216;
        uint32_t Vb = sbase + 36864 + st * 9216;

        float sacc[8][4];
        #pragma unroll
        for (int nt = 0; nt < 8; nt++)
            #pragma unroll
            for (int q = 0; q < 4; q++) sacc[nt][q] = 0.f;

        #pragma unroll
        for (int j = 0; j < 4; j++) {
            #pragma unroll
            for (int p = 0; p < 4; p++) {
                uint32_t bf[4];
                ldm_x4(bf, Kb + (p * 16 + bnrow) * QPITCH + (j * 2 + bcsel) * 16);
                mma_bf16(sacc[2 * p],     qf[j], bf[0], bf[1]);
                mma_bf16(sacc[2 * p + 1], qf[j], bf[2], bf[3]);
            }
        }

        // exp-group g -> pf[g]; PV j-outer so exp(j+1) (MUFU) overlaps PV(j) (HMMA)
        uint32_t pf[4][4];
        #define EXPGRP(g) do { \
            float e00 = ex2f(sacc[2*(g)][0]),   e01 = ex2f(sacc[2*(g)][1]); \
            float e02 = ex2f(sacc[2*(g)][2]),   e03 = ex2f(sacc[2*(g)][3]); \
            float e10 = ex2f(sacc[2*(g)+1][0]), e11 = ex2f(sacc[2*(g)+1][1]); \
            float e12 = ex2f(sacc[2*(g)+1][2]), e13 = ex2f(sacc[2*(g)+1][3]); \
            l0 += e00 + e01 + e10 + e11; \
            l1 += e02 + e03 + e12 + e13; \
            pf[g][0] = pack_bf2(e00, e01); \
            pf[g][1] = pack_bf2(e02, e03); \
            pf[g][2] = pack_bf2(e10, e11); \
            pf[g][3] = pack_bf2(e12, e13); \
        } while (0)

        EXPGRP(0);
        #pragma unroll
        for (int j = 0; j < 4; j++) {
            if (j < 3) EXPGRP(j + 1);
            #pragma unroll
            for (int p = 0; p < 4; p++) {
                uint32_t vf[4];
                ldm_x4t(vf, Vb + (j * 16 + vkey) * QPITCH + (p * 2 + vcsel) * 16);
                mma_bf16(oacc[2 * p],     pf[j], vf[0], vf[1]);
                mma_bf16(oacc[2 * p + 1], pf[j], vf[2], vf[3]);
            }
        }
        #undef EXPGRP
    }

    l0 += __shfl_xor_sync(0xffffffffu, l0, 1);
    l0 += __shfl_xor_sync(0xffffffffu, l0, 2);
    l1 += __shfl_xor_sync(0xffffffffu, l1, 1);
    l1 += __shfl_xor_sync(0xffffffffu, l1, 2);
    float inv0 = 1.f / l0, inv1 = 1.f / l1;

    int ob = bh & 15, oh = bh >> 4;   // reference's head-major permutation
    int r = q0 + w * 16 + (lane >> 2);
    __nv_bfloat16* d0 = g_attnT + ((size_t)ob * HW + r) * C_ + oh * 64;
    __nv_bfloat16* d1 = g_attnT + ((size_t)ob * HW + r + 8) * C_ + oh * 64;
    #pragma unroll
    for (int nt = 0; nt < 8; nt++) {
        int ch = nt * 8 + (lane & 3) * 2;
        *(__nv_bfloat162*)(d0 + ch) = __floats2bfloat162_rn(oacc[nt][0] * inv0, oacc[nt][1] * inv0);
        *(__nv_bfloat162*)(d1 + ch) = __floats2bfloat162_rn(oacc[nt][2] * inv1, oacc[nt][3] * inv1);
    }
}

// ---------------- launch ----------------
extern "C" void kernel_launch(void* const* d_in, const int* in_sizes, int n_in,
                              void* d_out, int out_size) {
    const float* x      = (const float*)d_in[0];
    const float* gamma  = (const float*)d_in[1];
    const float* beta   = (const float*)d_in[2];
    const float* w_qkv  = (const float*)d_in[3];
    const float* b_qkv  = (const float*)d_in[4];
    const float* w_proj = (const float*)d_in[5];
    const float* b_proj = (const float*)d_in[6];
    float* out = (float*)d_out;

    cudaFuncSetAttribute(attn_kernel, cudaFuncAttributeMaxDynamicSharedMemorySize, ATTN_SMEM);

    gn_kernel<<<B_ * 32, 256>>>(x, gamma, beta, w_qkv, w_proj);
    {
        dim3 grid((3 * C_) / 128, HW / 128, B_);   // 12 x 8 x 16
        gemm_kernel<<<grid, 256, GEMM_SMEM>>>(0, b_qkv, nullptr, nullptr);
    }
    {
        dim3 grid(HW / 128, B_ * 8);               // 8 x 128
        attn_kernel<<<grid, 256, ATTN_SMEM>>>();
    }
    {
        dim3 grid(HW / 128, C_ / 128, B_);         // 8 x 4 x 16
        gemm_kernel<<<grid, 256, GEMM_SMEM>>>(1, b_proj, x, out);
    }
}

// round 13
// speedup vs baseline: 1.2829x; 1.2829x over previous
#include <cuda_runtime.h>
#include <cuda_bf16.h>
#include <cstdint>

#define B_  16
#define C_  512
#define HW  1024
// 512^-0.5 * log2(e): scores land in log2 domain -> softmax uses raw ex2
#define QSCALE_F 0.06376237874911709f

// ---------------- scratch (device globals) ----------------
__device__ __nv_bfloat16 g_hT  [(size_t)B_ * HW * C_];      // [b][pos][ch]
__device__ __nv_bfloat16 g_qkvT[(size_t)B_ * HW * 3 * C_];  // [b][pos][och], q pre-scaled by QSCALE
__device__ __nv_bfloat16 g_attnT[(size_t)B_ * HW * C_];     // [b][pos][ch] (head-major permuted)
__device__ __nv_bfloat16 g_wqkv[(size_t)3 * C_ * C_];       // [och][ch]
__device__ __nv_bfloat16 g_wproj[(size_t)C_ * C_];          // [och][ch]

// ---------------- helpers ----------------
__device__ __forceinline__ uint32_t smem_u32(const void* p) {
    uint32_t a;
    asm("{ .reg .u64 t; cvta.to.shared.u64 t, %1; cvt.u32.u64 %0, t; }" : "=r"(a) : "l"(p));
    return a;
}
#define CP16(dst, src) asm volatile("cp.async.cg.shared.global [%0], [%1], 16;" :: "r"(dst), "l"(src))
#define CP_COMMIT()    asm volatile("cp.async.commit_group;" ::: "memory")
#define CP_WAIT(n)     asm volatile("cp.async.wait_group %0;" :: "n"(n) : "memory")

__device__ __forceinline__ void ldm_x4(uint32_t* r, uint32_t a) {
    asm volatile("ldmatrix.sync.aligned.m8n8.x4.shared.b16 {%0,%1,%2,%3}, [%4];"
        : "=r"(r[0]), "=r"(r[1]), "=r"(r[2]), "=r"(r[3]) : "r"(a));
}
__device__ __forceinline__ void ldm_x4t(uint32_t* r, uint32_t a) {
    asm volatile("ldmatrix.sync.aligned.m8n8.x4.trans.shared.b16 {%0,%1,%2,%3}, [%4];"
        : "=r"(r[0]), "=r"(r[1]), "=r"(r[2]), "=r"(r[3]) : "r"(a));
}
__device__ __forceinline__ void mma_bf16(float* d, const uint32_t* a, uint32_t b0, uint32_t b1) {
    asm volatile("mma.sync.aligned.m16n8k16.row.col.f32.bf16.bf16.f32 "
        "{%0,%1,%2,%3}, {%4,%5,%6,%7}, {%8,%9}, {%0,%1,%2,%3};"
        : "+f"(d[0]), "+f"(d[1]), "+f"(d[2]), "+f"(d[3])
        : "r"(a[0]), "r"(a[1]), "r"(a[2]), "r"(a[3]), "r"(b0), "r"(b1));
}
__device__ __forceinline__ uint32_t pack_bf2(float lo, float hi) {
    __nv_bfloat162 t = __floats2bfloat162_rn(lo, hi);
    return *(uint32_t*)&t;
}
__device__ __forceinline__ float ex2f(float x) {
    float r;
    asm("ex2.approx.ftz.f32 %0, %1;" : "=f"(r) : "f"(x));
    return r;
}

// ---------------- GroupNorm -> transposed bf16 (+ fused weight convert) ----------------
__global__ __launch_bounds__(256) void gn_kernel(const float* __restrict__ x,
                                                 const float* __restrict__ gamma,
                                                 const float* __restrict__ beta,
                                                 const float* __restrict__ wq,
                                                 const float* __restrict__ wp) {
    int bg = blockIdx.x;
    int b = bg >> 5, g = bg & 31;

    // fused weight conversion: 2048 elements per block (1,048,576 total / 512 blocks)
    {
        int base = bg * 2048 + threadIdx.x;
        #pragma unroll
        for (int i = 0; i < 8; i++) {
            int idx = base + i * 256;
            if (idx < 3 * C_ * C_) g_wqkv[idx] = __float2bfloat16_rn(wq[idx]);
            else                   g_wproj[idx - 3 * C_ * C_] = __float2bfloat16_rn(wp[idx - 3 * C_ * C_]);
        }
    }

    const float* xp = x + ((size_t)b * C_ + g * 16) * HW;
    float s = 0.f, s2 = 0.f;
    for (int i = threadIdx.x; i < 16 * HW; i += 256) { float v = xp[i]; s += v; s2 += v * v; }
    __shared__ float rs[256], rs2[256];
    __shared__ float sgam[16], sbet[16];
    rs[threadIdx.x] = s; rs2[threadIdx.x] = s2;
    if (threadIdx.x < 16) { sgam[threadIdx.x] = gamma[g * 16 + threadIdx.x];
                            sbet[threadIdx.x] = beta [g * 16 + threadIdx.x]; }
    __syncthreads();
    for (int o = 128; o > 0; o >>= 1) {
        if (threadIdx.x < o) { rs[threadIdx.x] += rs[threadIdx.x + o]; rs2[threadIdx.x] += rs2[threadIdx.x + o]; }
        __syncthreads();
    }
    float mean = rs[0] * (1.f / 16384.f);
    float var  = rs2[0] * (1.f / 16384.f) - mean * mean;
    float inv  = rsqrtf(var + 1e-5f);
    for (int pp = 0; pp < 4; pp++) {
        int pos = pp * 256 + threadIdx.x;
        __nv_bfloat16 o16[16];
        #pragma unroll
        for (int c = 0; c < 16; c++)
            o16[c] = __float2bfloat16_rn((xp[c * HW + pos] - mean) * inv * sgam[c] + sbet[c]);
        __nv_bfloat16* dst = g_hT + ((size_t)b * HW + pos) * C_ + g * 16;
        *(uint4*)dst       = *(uint4*)&o16[0];
        *(uint4*)(dst + 8) = *(uint4*)&o16[8];
    }
}

// ---------------- GEMM via mma.sync: tile 128x128, k-chunk 32, DB, 1 sync/iter (R7) ----------
// pitch 80B; A stages @0/@10240, B stages @20480/@30720; total 40960
#define GEMM_SMEM 40960

__global__ __launch_bounds__(256) void gemm_kernel(int mode, const float* __restrict__ bias,
                                                   const float* __restrict__ xres,
                                                   float* __restrict__ out) {
    extern __shared__ char smraw[];
    uint32_t sbase = smem_u32(smraw);
    int b = blockIdx.z;
    int n0 = blockIdx.x * 128, m0 = blockIdx.y * 128;
    const __nv_bfloat16 *gA, *gB;
    if (mode == 0) { gA = g_hT + ((size_t)b * HW + m0) * C_;  gB = g_wqkv + (size_t)n0 * C_; }
    else           { gA = g_wproj + (size_t)m0 * C_;          gB = g_attnT + ((size_t)b * HW + n0) * C_; }

    int tid = threadIdx.x, w = tid >> 5, lane = tid & 31;
    int wm = w >> 1, wn = w & 1;

    float acc[2][8][4];
    #pragma unroll
    for (int mt = 0; mt < 2; mt++)
        #pragma unroll
        for (int nt = 0; nt < 8; nt++)
            #pragma unroll
            for (int q = 0; q < 4; q++) acc[mt][nt][q] = 0.f;

    int lrow = tid >> 1, lcc = (tid & 1) * 2;
    const __nv_bfloat16* gArow = gA + (size_t)lrow * C_ + lcc * 8;
    const __nv_bfloat16* gBrow = gB + (size_t)lrow * C_ + lcc * 8;
    uint32_t sA = sbase + lrow * 80 + lcc * 16;
    uint32_t sB = sbase + 20480 + lrow * 80 + lcc * 16;

    CP16(sA, gArow); CP16(sA + 16, gArow + 8);
    CP16(sB, gBrow); CP16(sB + 16, gBrow + 8);
    CP_COMMIT();

    int arow = lane & 15, asel = lane >> 4;
    int bnrow = (lane & 7) + ((lane >> 4) << 3), bcsel = (lane >> 3) & 1;

    for (int kc = 0; kc < 16; kc++) {
        int st = kc & 1;
        CP_WAIT(0);
        __syncthreads();
        if (kc < 15) {
            int nst = st ^ 1;
            const __nv_bfloat16* a2 = gArow + (kc + 1) * 32;
            const __nv_bfloat16* b2 = gBrow + (kc + 1) * 32;
            uint32_t dA = sA + nst * 10240, dB = sB + nst * 10240;
            CP16(dA, a2); CP16(dA + 16, a2 + 8);
            CP16(dB, b2); CP16(dB + 16, b2 + 8);
            CP_COMMIT();
        }
        uint32_t Ab = sbase + st * 10240;
        uint32_t Bb = sbase + 20480 + st * 10240;
        #pragma unroll
        for (int j = 0; j < 2; j++) {
            uint32_t af[2][4];
            #pragma unroll
            for (int mt = 0; mt < 2; mt++)
                ldm_x4(af[mt], Ab + (wm * 32 + mt * 16 + arow) * 80 + (j * 2 + asel) * 16);
            #pragma unroll
            for (int p = 0; p < 4; p++) {
                uint32_t bf[4];
                ldm_x4(bf, Bb + (wn * 64 + p * 16 + bnrow) * 80 + (j * 2 + bcsel) * 16);
                #pragma unroll
                for (int mt = 0; mt < 2; mt++) {
                    mma_bf16(acc[mt][2 * p],     af[mt], bf[0], bf[1]);
                    mma_bf16(acc[mt][2 * p + 1], af[mt], bf[2], bf[3]);
                }
            }
        }
    }

    int r0 = m0 + wm * 32 + (lane >> 2);
    if (mode == 0) {
        #pragma unroll
        for (int mt = 0; mt < 2; mt++) {
            int r = r0 + mt * 16;
            #pragma unroll
            for (int nt = 0; nt < 8; nt++) {
                int col = n0 + wn * 64 + nt * 8 + (lane & 3) * 2;
                float b0v = bias[col], b1v = bias[col + 1];
                float sc = ((col % 192) < 64) ? QSCALE_F : 1.f;
                *(__nv_bfloat162*)&g_qkvT[((size_t)b * HW + r) * 1536 + col] =
                    __floats2bfloat162_rn((acc[mt][nt][0] + b0v) * sc, (acc[mt][nt][1] + b1v) * sc);
                *(__nv_bfloat162*)&g_qkvT[((size_t)b * HW + r + 8) * 1536 + col] =
                    __floats2bfloat162_rn((acc[mt][nt][2] + b0v) * sc, (acc[mt][nt][3] + b1v) * sc);
            }
        }
    } else {
        // batch all residual loads first (MLP), then stores
        #pragma unroll
        for (int mt = 0; mt < 2; mt++) {
            int r = r0 + mt * 16;
            float2 xa[8], xb[8];
            #pragma unroll
            for (int nt = 0; nt < 8; nt++) {
                int col = n0 + wn * 64 + nt * 8 + (lane & 3) * 2;
                xa[nt] = *(const float2*)(xres + ((size_t)b * C_ + r) * HW + col);
                xb[nt] = *(const float2*)(xres + ((size_t)b * C_ + r + 8) * HW + col);
            }
            float bi0 = bias[r], bi1 = bias[r + 8];
            #pragma unroll
            for (int nt = 0; nt < 8; nt++) {
                int col = n0 + wn * 64 + nt * 8 + (lane & 3) * 2;
                float2 o0 = { acc[mt][nt][0] + bi0 + xa[nt].x, acc[mt][nt][1] + bi0 + xa[nt].y };
                float2 o1 = { acc[mt][nt][2] + bi1 + xb[nt].x, acc[mt][nt][3] + bi1 + xb[nt].y };
                *(float2*)(out + ((size_t)b * C_ + r) * HW + col)     = o0;
                *(float2*)(out + ((size_t)b * C_ + r + 8) * HW + col) = o1;
            }
        }
    }
}

// ---------------- fused attention (R7: flash-style, log2 softmax, exp/mma overlap, DB) --------
// smem: Q[128][144B]@0 (18432), K stages @18432+st*9216, V stages @36864+st*9216; total 55296
#define QPITCH 144
#define ATTN_SMEM 55296

__global__ __launch_bounds__(256) void attn_kernel() {
    extern __shared__ char smraw[];
    uint32_t sbase = smem_u32(smraw);
    int bh = blockIdx.y, bb = bh >> 3, head = bh & 7;
    int q0 = blockIdx.x * 128;
    int tid = threadIdx.x, w = tid >> 5, lane = tid & 31;
    const __nv_bfloat16* qkvb = g_qkvT + (size_t)bb * HW * 1536;
    int hb = head * 192;

    // Q tile (q pre-scaled by 512^-0.5 * log2e in qkv epilogue)
    {
        int row = tid >> 1, c0 = (tid & 1) * 4;
        const __nv_bfloat16* src = qkvb + (size_t)(q0 + row) * 1536 + hb + c0 * 8;
        uint32_t dst = sbase + row * QPITCH + c0 * 16;
        CP16(dst, src); CP16(dst + 16, src + 8); CP16(dst + 32, src + 16); CP16(dst + 48, src + 24);
    }
    int kvrow = tid >> 2, kvc = (tid & 3) * 2;
    const __nv_bfloat16* gK = qkvb + hb + 64;
    const __nv_bfloat16* gV = qkvb + hb + 128;
    {
        const __nv_bfloat16* ks = gK + (size_t)kvrow * 1536 + kvc * 8;
        const __nv_bfloat16* vs = gV + (size_t)kvrow * 1536 + kvc * 8;
        uint32_t kd = sbase + 18432 + kvrow * QPITCH + kvc * 16;
        uint32_t vd = sbase + 36864 + kvrow * QPITCH + kvc * 16;
        CP16(kd, ks); CP16(kd + 16, ks + 8);
        CP16(vd, vs); CP16(vd + 16, vs + 8);
    }
    CP_COMMIT();

    uint32_t qf[4][4];
    float oacc[8][4];
    #pragma unroll
    for (int nt = 0; nt < 8; nt++)
        #pragma unroll
        for (int q = 0; q < 4; q++) oacc[nt][q] = 0.f;
    float l0 = 0.f, l1 = 0.f;

    int arow = lane & 15, asel = lane >> 4;
    int bnrow = (lane & 7) + ((lane >> 4) << 3), bcsel = (lane >> 3) & 1; // K non-trans
    int vkey  = (lane & 7) + (((lane >> 3) & 1) << 3), vcsel = lane >> 4; // V trans

    for (int kc = 0; kc < 16; kc++) {
        int st = kc & 1;
        CP_WAIT(0);
        __syncthreads();
        if (kc == 0) {   // Q resident: load register fragments once
            #pragma unroll
            for (int j = 0; j < 4; j++)
                ldm_x4(qf[j], sbase + (w * 16 + arow) * QPITCH + (j * 2 + asel) * 16);
        }
        if (kc < 15) {
            int nst = st ^ 1;
            const __nv_bfloat16* ks = gK + (size_t)((kc + 1) * 64 + kvrow) * 1536 + kvc * 8;
            const __nv_bfloat16* vs = gV + (size_t)((kc + 1) * 64 + kvrow) * 1536 + kvc * 8;
            uint32_t kd = sbase + 18432 + nst * 9216 + kvrow * QPITCH + kvc * 16;
            uint32_t vd = sbase + 36864 + nst * 9216 + kvrow * QPITCH + kvc * 16;
            CP16(kd, ks); CP16(kd + 16, ks + 8);
            CP16(vd, vs); CP16(vd + 16, vs + 8);
            CP_COMMIT();
        }

        uint32_t Kb = sbase + 18432 + st * 9216;
        uint32_t Vb = sbase + 36864 + st * 9216;

        float sacc[8][4];
        #pragma unroll
        for (int nt = 0; nt < 8; nt++)
            #pragma unroll
            for (int q = 0; q < 4; q++) sacc[nt][q] = 0.f;

        #pragma unroll
        for (int j = 0; j < 4; j++) {
            #pragma unroll
            for (int p = 0; p < 4; p++) {
                uint32_t bf[4];
                ldm_x4(bf, Kb + (p * 16 + bnrow) * QPITCH + (j * 2 + bcsel) * 16);
                mma_bf16(sacc[2 * p],     qf[j], bf[0], bf[1]);
                mma_bf16(sacc[2 * p + 1], qf[j], bf[2], bf[3]);
            }
        }

        // exp-group g -> pf[g]; PV j-outer so exp(j+1) (MUFU) overlaps PV(j) (HMMA)
        uint32_t pf[4][4];
        #define EXPGRP(g) do { \
            float e00 = ex2f(sacc[2*(g)][0]),   e01 = ex2f(sacc[2*(g)][1]); \
            float e02 = ex2f(sacc[2*(g)][2]),   e03 = ex2f(sacc[2*(g)][3]); \
            float e10 = ex2f(sacc[2*(g)+1][0]), e11 = ex2f(sacc[2*(g)+1][1]); \
            float e12 = ex2f(sacc[2*(g)+1][2]), e13 = ex2f(sacc[2*(g)+1][3]); \
            l0 += e00 + e01 + e10 + e11; \
            l1 += e02 + e03 + e12 + e13; \
            pf[g][0] = pack_bf2(e00, e01); \
            pf[g][1] = pack_bf2(e02, e03); \
            pf[g][2] = pack_bf2(e10, e11); \
            pf[g][3] = pack_bf2(e12, e13); \
        } while (0)

        EXPGRP(0);
        #pragma unroll
        for (int j = 0; j < 4; j++) {
            if (j < 3) EXPGRP(j + 1);
            #pragma unroll
            for (int p = 0; p < 4; p++) {
                uint32_t vf[4];
                ldm_x4t(vf, Vb + (j * 16 + vkey) * QPITCH + (p * 2 + vcsel) * 16);
                mma_bf16(oacc[2 * p],     pf[j], vf[0], vf[1]);
                mma_bf16(oacc[2 * p + 1], pf[j], vf[2], vf[3]);
            }
        }
        #undef EXPGRP
    }

    l0 += __shfl_xor_sync(0xffffffffu, l0, 1);
    l0 += __shfl_xor_sync(0xffffffffu, l0, 2);
    l1 += __shfl_xor_sync(0xffffffffu, l1, 1);
    l1 += __shfl_xor_sync(0xffffffffu, l1, 2);
    float inv0 = 1.f / l0, inv1 = 1.f / l1;

    int ob = bh & 15, oh = bh >> 4;   // reference's head-major permutation
    int r = q0 + w * 16 + (lane >> 2);
    __nv_bfloat16* d0 = g_attnT + ((size_t)ob * HW + r) * C_ + oh * 64;
    __nv_bfloat16* d1 = g_attnT + ((size_t)ob * HW + r + 8) * C_ + oh * 64;
    #pragma unroll
    for (int nt = 0; nt < 8; nt++) {
        int ch = nt * 8 + (lane & 3) * 2;
        *(__nv_bfloat162*)(d0 + ch) = __floats2bfloat162_rn(oacc[nt][0] * inv0, oacc[nt][1] * inv0);
        *(__nv_bfloat162*)(d1 + ch) = __floats2bfloat162_rn(oacc[nt][2] * inv1, oacc[nt][3] * inv1);
    }
}

// ---------------- launch ----------------
extern "C" void kernel_launch(void* const* d_in, const int* in_sizes, int n_in,
                              void* d_out, int out_size) {
    const float* x      = (const float*)d_in[0];
    const float* gamma  = (const float*)d_in[1];
    const float* beta   = (const float*)d_in[2];
    const float* w_qkv  = (const float*)d_in[3];
    const float* b_qkv  = (const float*)d_in[4];
    const float* w_proj = (const float*)d_in[5];
    const float* b_proj = (const float*)d_in[6];
    float* out = (float*)d_out;

    cudaFuncSetAttribute(attn_kernel, cudaFuncAttributeMaxDynamicSharedMemorySize, ATTN_SMEM);

    gn_kernel<<<B_ * 32, 256>>>(x, gamma, beta, w_qkv, w_proj);
    {
        dim3 grid((3 * C_) / 128, HW / 128, B_);   // 12 x 8 x 16
        gemm_kernel<<<grid, 256, GEMM_SMEM>>>(0, b_qkv, nullptr, nullptr);
    }
    {
        dim3 grid(HW / 128, B_ * 8);               // 8 x 128
        attn_kernel<<<grid, 256, ATTN_SMEM>>>();
    }
    {
        dim3 grid(HW / 128, C_ / 128, B_);         // 8 x 4 x 16
        gemm_kernel<<<grid, 256, GEMM_SMEM>>>(1, b_proj, x, out);
    }
}

// round 14
// speedup vs baseline: 1.3172x; 1.0267x over previous
#include <cuda_runtime.h>
#include <cuda_bf16.h>
#include <cstdint>

#define B_  16
#define C_  512
#define HW  1024
// 512^-0.5 * log2(e): scores land in log2 domain -> softmax uses raw ex2
#define QSCALE_F 0.06376237874911709f

// ---------------- scratch (device globals) ----------------
__device__ __nv_bfloat16 g_hT  [(size_t)B_ * HW * C_];      // [b][pos][ch]
__device__ __nv_bfloat16 g_qkvT[(size_t)B_ * HW * 3 * C_];  // [b][pos][och], q pre-scaled by QSCALE
__device__ __nv_bfloat16 g_attnT[(size_t)B_ * HW * C_];     // [b][pos][ch] (head-major permuted)
__device__ __nv_bfloat16 g_wqkv[(size_t)3 * C_ * C_];       // [och][ch]
__device__ __nv_bfloat16 g_wproj[(size_t)C_ * C_];          // [och][ch]

// ---------------- stream/event resources (created at static init; no device mem alloc) -------
static cudaStream_t g_s1 = nullptr;
static cudaEvent_t  g_e0 = nullptr, g_e1 = nullptr;
namespace {
struct ResInit {
    ResInit() {
        if (cudaStreamCreateWithFlags(&g_s1, cudaStreamNonBlocking) != cudaSuccess) g_s1 = nullptr;
        if (cudaEventCreateWithFlags(&g_e0, cudaEventDisableTiming) != cudaSuccess) g_e0 = nullptr;
        if (cudaEventCreateWithFlags(&g_e1, cudaEventDisableTiming) != cudaSuccess) g_e1 = nullptr;
    }
};
static ResInit g_resinit;
}

// ---------------- helpers ----------------
__device__ __forceinline__ uint32_t smem_u32(const void* p) {
    uint32_t a;
    asm("{ .reg .u64 t; cvta.to.shared.u64 t, %1; cvt.u32.u64 %0, t; }" : "=r"(a) : "l"(p));
    return a;
}
#define CP16(dst, src) asm volatile("cp.async.cg.shared.global [%0], [%1], 16;" :: "r"(dst), "l"(src))
#define CP_COMMIT()    asm volatile("cp.async.commit_group;" ::: "memory")
#define CP_WAIT(n)     asm volatile("cp.async.wait_group %0;" :: "n"(n) : "memory")

__device__ __forceinline__ void ldm_x4(uint32_t* r, uint32_t a) {
    asm volatile("ldmatrix.sync.aligned.m8n8.x4.shared.b16 {%0,%1,%2,%3}, [%4];"
        : "=r"(r[0]), "=r"(r[1]), "=r"(r[2]), "=r"(r[3]) : "r"(a));
}
__device__ __forceinline__ void ldm_x4t(uint32_t* r, uint32_t a) {
    asm volatile("ldmatrix.sync.aligned.m8n8.x4.trans.shared.b16 {%0,%1,%2,%3}, [%4];"
        : "=r"(r[0]), "=r"(r[1]), "=r"(r[2]), "=r"(r[3]) : "r"(a));
}
__device__ __forceinline__ void mma_bf16(float* d, const uint32_t* a, uint32_t b0, uint32_t b1) {
    asm volatile("mma.sync.aligned.m16n8k16.row.col.f32.bf16.bf16.f32 "
        "{%0,%1,%2,%3}, {%4,%5,%6,%7}, {%8,%9}, {%0,%1,%2,%3};"
        : "+f"(d[0]), "+f"(d[1]), "+f"(d[2]), "+f"(d[3])
        : "r"(a[0]), "r"(a[1]), "r"(a[2]), "r"(a[3]), "r"(b0), "r"(b1));
}
__device__ __forceinline__ uint32_t pack_bf2(float lo, float hi) {
    __nv_bfloat162 t = __floats2bfloat162_rn(lo, hi);
    return *(uint32_t*)&t;
}
__device__ __forceinline__ float ex2f(float x) {
    float r;
    asm("ex2.approx.ftz.f32 %0, %1;" : "=f"(r) : "f"(x));
    return r;
}

// ---------------- weight convert (before the fork; both branches depend on it) ----------------
__global__ __launch_bounds__(256) void conv_kernel(const float* __restrict__ wq,
                                                   const float* __restrict__ wp) {
    int i = blockIdx.x * 256 + threadIdx.x;
    if (i < 3 * C_ * C_) g_wqkv[i]  = __float2bfloat16_rn(wq[i]);
    if (i < C_ * C_)     g_wproj[i] = __float2bfloat16_rn(wp[i]);
}

// ---------------- GroupNorm -> transposed bf16 (batch-half via offset) ----------------
__global__ __launch_bounds__(256) void gn_kernel(const float* __restrict__ x,
                                                 const float* __restrict__ gamma,
                                                 const float* __restrict__ beta,
                                                 int boff) {
    int bg = blockIdx.x;
    int b = (bg >> 5) + boff, g = bg & 31;

    const float* xp = x + ((size_t)b * C_ + g * 16) * HW;
    float s = 0.f, s2 = 0.f;
    for (int i = threadIdx.x; i < 16 * HW; i += 256) { float v = xp[i]; s += v; s2 += v * v; }
    __shared__ float rs[256], rs2[256];
    __shared__ float sgam[16], sbet[16];
    rs[threadIdx.x] = s; rs2[threadIdx.x] = s2;
    if (threadIdx.x < 16) { sgam[threadIdx.x] = gamma[g * 16 + threadIdx.x];
                            sbet[threadIdx.x] = beta [g * 16 + threadIdx.x]; }
    __syncthreads();
    for (int o = 128; o > 0; o >>= 1) {
        if (threadIdx.x < o) { rs[threadIdx.x] += rs[threadIdx.x + o]; rs2[threadIdx.x] += rs2[threadIdx.x + o]; }
        __syncthreads();
    }
    float mean = rs[0] * (1.f / 16384.f);
    float var  = rs2[0] * (1.f / 16384.f) - mean * mean;
    float inv  = rsqrtf(var + 1e-5f);
    for (int pp = 0; pp < 4; pp++) {
        int pos = pp * 256 + threadIdx.x;
        __nv_bfloat16 o16[16];
        #pragma unroll
        for (int c = 0; c < 16; c++)
            o16[c] = __float2bfloat16_rn((xp[c * HW + pos] - mean) * inv * sgam[c] + sbet[c]);
        __nv_bfloat16* dst = g_hT + ((size_t)b * HW + pos) * C_ + g * 16;
        *(uint4*)dst       = *(uint4*)&o16[0];
        *(uint4*)(dst + 8) = *(uint4*)&o16[8];
    }
}

// ---------------- GEMM via mma.sync: tile 128x128, k-chunk 32, DB, 1 sync/iter (R13) ----------
// pitch 80B; A stages @0/@10240, B stages @20480/@30720; total 40960
#define GEMM_SMEM 40960

__global__ __launch_bounds__(256) void gemm_kernel(int mode, const float* __restrict__ bias,
                                                   const float* __restrict__ xres,
                                                   float* __restrict__ out, int boff) {
    extern __shared__ char smraw[];
    uint32_t sbase = smem_u32(smraw);
    int b = blockIdx.z + boff;
    int n0 = blockIdx.x * 128, m0 = blockIdx.y * 128;
    const __nv_bfloat16 *gA, *gB;
    if (mode == 0) { gA = g_hT + ((size_t)b * HW + m0) * C_;  gB = g_wqkv + (size_t)n0 * C_; }
    else           { gA = g_wproj + (size_t)m0 * C_;          gB = g_attnT + ((size_t)b * HW + n0) * C_; }

    int tid = threadIdx.x, w = tid >> 5, lane = tid & 31;
    int wm = w >> 1, wn = w & 1;

    float acc[2][8][4];
    #pragma unroll
    for (int mt = 0; mt < 2; mt++)
        #pragma unroll
        for (int nt = 0; nt < 8; nt++)
            #pragma unroll
            for (int q = 0; q < 4; q++) acc[mt][nt][q] = 0.f;

    int lrow = tid >> 1, lcc = (tid & 1) * 2;
    const __nv_bfloat16* gArow = gA + (size_t)lrow * C_ + lcc * 8;
    const __nv_bfloat16* gBrow = gB + (size_t)lrow * C_ + lcc * 8;
    uint32_t sA = sbase + lrow * 80 + lcc * 16;
    uint32_t sB = sbase + 20480 + lrow * 80 + lcc * 16;

    CP16(sA, gArow); CP16(sA + 16, gArow + 8);
    CP16(sB, gBrow); CP16(sB + 16, gBrow + 8);
    CP_COMMIT();

    int arow = lane & 15, asel = lane >> 4;
    int bnrow = (lane & 7) + ((lane >> 4) << 3), bcsel = (lane >> 3) & 1;

    for (int kc = 0; kc < 16; kc++) {
        int st = kc & 1;
        CP_WAIT(0);
        __syncthreads();
        if (kc < 15) {
            int nst = st ^ 1;
            const __nv_bfloat16* a2 = gArow + (kc + 1) * 32;
            const __nv_bfloat16* b2 = gBrow + (kc + 1) * 32;
            uint32_t dA = sA + nst * 10240, dB = sB + nst * 10240;
            CP16(dA, a2); CP16(dA + 16, a2 + 8);
            CP16(dB, b2); CP16(dB + 16, b2 + 8);
            CP_COMMIT();
        }
        uint32_t Ab = sbase + st * 10240;
        uint32_t Bb = sbase + 20480 + st * 10240;
        #pragma unroll
        for (int j = 0; j < 2; j++) {
            uint32_t af[2][4];
            #pragma unroll
            for (int mt = 0; mt < 2; mt++)
                ldm_x4(af[mt], Ab + (wm * 32 + mt * 16 + arow) * 80 + (j * 2 + asel) * 16);
            #pragma unroll
            for (int p = 0; p < 4; p++) {
                uint32_t bf[4];
                ldm_x4(bf, Bb + (wn * 64 + p * 16 + bnrow) * 80 + (j * 2 + bcsel) * 16);
                #pragma unroll
                for (int mt = 0; mt < 2; mt++) {
                    mma_bf16(acc[mt][2 * p],     af[mt], bf[0], bf[1]);
                    mma_bf16(acc[mt][2 * p + 1], af[mt], bf[2], bf[3]);
                }
            }
        }
    }

    int r0 = m0 + wm * 32 + (lane >> 2);
    if (mode == 0) {
        #pragma unroll
        for (int mt = 0; mt < 2; mt++) {
            int r = r0 + mt * 16;
            #pragma unroll
            for (int nt = 0; nt < 8; nt++) {
                int col = n0 + wn * 64 + nt * 8 + (lane & 3) * 2;
                float b0v = bias[col], b1v = bias[col + 1];
                float sc = ((col % 192) < 64) ? QSCALE_F : 1.f;
                *(__nv_bfloat162*)&g_qkvT[((size_t)b * HW + r) * 1536 + col] =
                    __floats2bfloat162_rn((acc[mt][nt][0] + b0v) * sc, (acc[mt][nt][1] + b1v) * sc);
                *(__nv_bfloat162*)&g_qkvT[((size_t)b * HW + r + 8) * 1536 + col] =
                    __floats2bfloat162_rn((acc[mt][nt][2] + b0v) * sc, (acc[mt][nt][3] + b1v) * sc);
            }
        }
    } else {
        // batch all residual loads first (MLP), then stores
        #pragma unroll
        for (int mt = 0; mt < 2; mt++) {
            int r = r0 + mt * 16;
            float2 xa[8], xb[8];
            #pragma unroll
            for (int nt = 0; nt < 8; nt++) {
                int col = n0 + wn * 64 + nt * 8 + (lane & 3) * 2;
                xa[nt] = *(const float2*)(xres + ((size_t)b * C_ + r) * HW + col);
                xb[nt] = *(const float2*)(xres + ((size_t)b * C_ + r + 8) * HW + col);
            }
            float bi0 = bias[r], bi1 = bias[r + 8];
            #pragma unroll
            for (int nt = 0; nt < 8; nt++) {
                int col = n0 + wn * 64 + nt * 8 + (lane & 3) * 2;
                float2 o0 = { acc[mt][nt][0] + bi0 + xa[nt].x, acc[mt][nt][1] + bi0 + xa[nt].y };
                float2 o1 = { acc[mt][nt][2] + bi1 + xb[nt].x, acc[mt][nt][3] + bi1 + xb[nt].y };
                *(float2*)(out + ((size_t)b * C_ + r) * HW + col)     = o0;
                *(float2*)(out + ((size_t)b * C_ + r + 8) * HW + col) = o1;
            }
        }
    }
}

// ---------------- fused attention (R13 structure; batch-half via bh offset) ------------------
// smem: Q[128][144B]@0 (18432), K stages @18432+st*9216, V stages @36864+st*9216; total 55296
#define QPITCH 144
#define ATTN_SMEM 55296

__global__ __launch_bounds__(256) void attn_kernel(int bhoff) {
    extern __shared__ char smraw[];
    uint32_t sbase = smem_u32(smraw);
    int bh = blockIdx.y + bhoff, bb = bh >> 3, head = bh & 7;
    int q0 = blockIdx.x * 128;
    int tid = threadIdx.x, w = tid >> 5, lane = tid & 31;
    const __nv_bfloat16* qkvb = g_qkvT + (size_t)bb * HW * 1536;
    int hb = head * 192;

    // Q tile (q pre-scaled by 512^-0.5 * log2e in qkv epilogue)
    {
        int row = tid >> 1, c0 = (tid & 1) * 4;
        const __nv_bfloat16* src = qkvb + (size_t)(q0 + row) * 1536 + hb + c0 * 8;
        uint32_t dst = sbase + row * QPITCH + c0 * 16;
        CP16(dst, src); CP16(dst + 16, src + 8); CP16(dst + 32, src + 16); CP16(dst + 48, src + 24);
    }
    int kvrow = tid >> 2, kvc = (tid & 3) * 2;
    const __nv_bfloat16* gK = qkvb + hb + 64;
    const __nv_bfloat16* gV = qkvb + hb + 128;
    {
        const __nv_bfloat16* ks = gK + (size_t)kvrow * 1536 + kvc * 8;
        const __nv_bfloat16* vs = gV + (size_t)kvrow * 1536 + kvc * 8;
        uint32_t kd = sbase + 18432 + kvrow * QPITCH + kvc * 16;
        uint32_t vd = sbase + 36864 + kvrow * QPITCH + kvc * 16;
        CP16(kd, ks); CP16(kd + 16, ks + 8);
        CP16(vd, vs); CP16(vd + 16, vs + 8);
    }
    CP_COMMIT();

    uint32_t qf[4][4];
    float oacc[8][4];
    #pragma unroll
    for (int nt = 0; nt < 8; nt++)
        #pragma unroll
        for (int q = 0; q < 4; q++) oacc[nt][q] = 0.f;
    float l0 = 0.f, l1 = 0.f;

    int arow = lane & 15, asel = lane >> 4;
    int bnrow = (lane & 7) + ((lane >> 4) << 3), bcsel = (lane >> 3) & 1; // K non-trans
    int vkey  = (lane & 7) + (((lane >> 3) & 1) << 3), vcsel = lane >> 4; // V trans

    for (int kc = 0; kc < 16; kc++) {
        int st = kc & 1;
        CP_WAIT(0);
        __syncthreads();
        if (kc == 0) {   // Q resident: load register fragments once
            #pragma unroll
            for (int j = 0; j < 4; j++)
                ldm_x4(qf[j], sbase + (w * 16 + arow) * QPITCH + (j * 2 + asel) * 16);
        }
        if (kc < 15) {
            int nst = st ^ 1;
            const __nv_bfloat16* ks = gK + (size_t)((kc + 1) * 64 + kvrow) * 1536 + kvc * 8;
            const __nv_bfloat16* vs = gV + (size_t)((kc + 1) * 64 + kvrow) * 1536 + kvc * 8;
            uint32_t kd = sbase + 18432 + nst * 9216 + kvrow * QPITCH + kvc * 16;
            uint32_t vd = sbase + 36864 + nst * 9216 + kvrow * QPITCH + kvc * 16;
            CP16(kd, ks); CP16(kd + 16, ks + 8);
            CP16(vd, vs); CP16(vd + 16, vs + 8);
            CP_COMMIT();
        }

        uint32_t Kb = sbase + 18432 + st * 9216;
        uint32_t Vb = sbase + 36864 + st * 9216;

        float sacc[8][4];
        #pragma unroll
        for (int nt = 0; nt < 8; nt++)
            #pragma unroll
            for (int q = 0; q < 4; q++) sacc[nt][q] = 0.f;

        #pragma unroll
        for (int j = 0; j < 4; j++) {
            #pragma unroll
            for (int p = 0; p < 4; p++) {
                uint32_t bf[4];
                ldm_x4(bf, Kb + (p * 16 + bnrow) * QPITCH + (j * 2 + bcsel) * 16);
                mma_bf16(sacc[2 * p],     qf[j], bf[0], bf[1]);
                mma_bf16(sacc[2 * p + 1], qf[j], bf[2], bf[3]);
            }
        }

        // exp-group g -> pf[g]; PV j-outer so exp(j+1) (MUFU) overlaps PV(j) (HMMA)
        uint32_t pf[4][4];
        #define EXPGRP(g) do { \
            float e00 = ex2f(sacc[2*(g)][0]),   e01 = ex2f(sacc[2*(g)][1]); \
            float e02 = ex2f(sacc[2*(g)][2]),   e03 = ex2f(sacc[2*(g)][3]); \
            float e10 = ex2f(sacc[2*(g)+1][0]), e11 = ex2f(sacc[2*(g)+1][1]); \
            float e12 = ex2f(sacc[2*(g)+1][2]), e13 = ex2f(sacc[2*(g)+1][3]); \
            l0 += e00 + e01 + e10 + e11; \
            l1 += e02 + e03 + e12 + e13; \
            pf[g][0] = pack_bf2(e00, e01); \
            pf[g][1] = pack_bf2(e02, e03); \
            pf[g][2] = pack_bf2(e10, e11); \
            pf[g][3] = pack_bf2(e12, e13); \
        } while (0)

        EXPGRP(0);
        #pragma unroll
        for (int j = 0; j < 4; j++) {
            if (j < 3) EXPGRP(j + 1);
            #pragma unroll
            for (int p = 0; p < 4; p++) {
                uint32_t vf[4];
                ldm_x4t(vf, Vb + (j * 16 + vkey) * QPITCH + (p * 2 + vcsel) * 16);
                mma_bf16(oacc[2 * p],     pf[j], vf[0], vf[1]);
                mma_bf16(oacc[2 * p + 1], pf[j], vf[2], vf[3]);
            }
        }
        #undef EXPGRP
    }

    l0 += __shfl_xor_sync(0xffffffffu, l0, 1);
    l0 += __shfl_xor_sync(0xffffffffu, l0, 2);
    l1 += __shfl_xor_sync(0xffffffffu, l1, 1);
    l1 += __shfl_xor_sync(0xffffffffu, l1, 2);
    float inv0 = 1.f / l0, inv1 = 1.f / l1;

    int ob = bh & 15, oh = bh >> 4;   // reference's head-major permutation
    int r = q0 + w * 16 + (lane >> 2);
    __nv_bfloat16* d0 = g_attnT + ((size_t)ob * HW + r) * C_ + oh * 64;
    __nv_bfloat16* d1 = g_attnT + ((size_t)ob * HW + r + 8) * C_ + oh * 64;
    #pragma unroll
    for (int nt = 0; nt < 8; nt++) {
        int ch = nt * 8 + (lane & 3) * 2;
        *(__nv_bfloat162*)(d0 + ch) = __floats2bfloat162_rn(oacc[nt][0] * inv0, oacc[nt][1] * inv0);
        *(__nv_bfloat162*)(d1 + ch) = __floats2bfloat162_rn(oacc[nt][2] * inv1, oacc[nt][3] * inv1);
    }
}

// ---------------- launch ----------------
extern "C" void kernel_launch(void* const* d_in, const int* in_sizes, int n_in,
                              void* d_out, int out_size) {
    const float* x      = (const float*)d_in[0];
    const float* gamma  = (const float*)d_in[1];
    const float* beta   = (const float*)d_in[2];
    const float* w_qkv  = (const float*)d_in[3];
    const float* b_qkv  = (const float*)d_in[4];
    const float* w_proj = (const float*)d_in[5];
    const float* b_proj = (const float*)d_in[6];
    float* out = (float*)d_out;

    cudaFuncSetAttribute(attn_kernel, cudaFuncAttributeMaxDynamicSharedMemorySize, ATTN_SMEM);

    bool pipelined = (g_s1 != nullptr) && (g_e0 != nullptr) && (g_e1 != nullptr);

    // weights converted before the fork (both branches need them)
    conv_kernel<<<(3 * C_ * C_ + 255) / 256, 256>>>(w_qkv, w_proj);

    if (pipelined) {
        cudaEventRecord(g_e0, 0);
        cudaStreamWaitEvent(g_s1, g_e0, 0);

        // branch A (stream 0): batches 0..7
        gn_kernel<<<256, 256>>>(x, gamma, beta, 0);
        {
            dim3 grid((3 * C_) / 128, HW / 128, 8);
            gemm_kernel<<<grid, 256, GEMM_SMEM>>>(0, b_qkv, nullptr, nullptr, 0);
        }
        {
            dim3 grid(HW / 128, 64);
            attn_kernel<<<grid, 256, ATTN_SMEM>>>(0);
        }

        // branch B (stream s1): batches 8..15
        gn_kernel<<<256, 256, 0, g_s1>>>(x, gamma, beta, 8);
        {
            dim3 grid((3 * C_) / 128, HW / 128, 8);
            gemm_kernel<<<grid, 256, GEMM_SMEM, g_s1>>>(0, b_qkv, nullptr, nullptr, 8);
        }
        {
            dim3 grid(HW / 128, 64);
            attn_kernel<<<grid, 256, ATTN_SMEM, g_s1>>>(8 * 64 / 8);   // bh offset 64
        }
        cudaEventRecord(g_e1, g_s1);
        cudaStreamWaitEvent(0, g_e1, 0);

        // join: proj needs ALL attn output (head-major scatter crosses batches)
        {
            dim3 grid(HW / 128, C_ / 128, B_);
            gemm_kernel<<<grid, 256, GEMM_SMEM>>>(1, b_proj, x, out, 0);
        }
    } else {
        // serial fallback (== R13 schedule)
        gn_kernel<<<256, 256>>>(x, gamma, beta, 0);
        gn_kernel<<<256, 256>>>(x, gamma, beta, 8);
        {
            dim3 grid((3 * C_) / 128, HW / 128, B_);
            gemm_kernel<<<grid, 256, GEMM_SMEM>>>(0, b_qkv, nullptr, nullptr, 0);
        }
        {
            dim3 grid(HW / 128, B_ * 8);
            attn_kernel<<<grid, 256, ATTN_SMEM>>>(0);
        }
        {
            dim3 grid(HW / 128, C_ / 128, B_);
            gemm_kernel<<<grid, 256, GEMM_SMEM>>>(1, b_proj, x, out, 0);
        }
    }
}